// round 8
// baseline (speedup 1.0000x reference)
#include <cuda_runtime.h>
#include <cuda_fp16.h>
#include <math.h>
#include <stdint.h>

#define HID  1024
#define FFN  4096
#define NE   8
#define NTOK 4096
#define CAP  9216

#define BM 128
#define BN 128
#define BK 32
#define STAGES 4                       // A-pipeline depth (cp.async)
#define APAD 40                        // halves per A smem row (80 B, conflict-free LDSM)
#define BPAD 136                       // halves per B smem k-row (272 B, conflict-free LDSM)
#define ABYTES (BM * APAD * 2)         // 10240
#define BBYTES (BK * BPAD * 2)         // 8704
#define A_TOT  (STAGES * ABYTES)       // 40960
#define SMEM_TOTAL (A_TOT + 2 * BBYTES)  // 58368 -> 2 CTAs/SM

// ---------------- scratch (device globals; zero-initialized at load) ----------------
__device__ int    g_cnt[NE];
__device__ int    g_off[NE + 1];
__device__ int    g_end[NE];
__device__ int    g_cur[NE];
__device__ int    g_rowTok[CAP];
__device__ int    g_tok2[NTOK * 2];
__device__ float  g_w2v[NTOK * 2];
__device__ int    g_pairPos[NTOK * 2];
__device__ __half g_Xh[(size_t)CAP * HID];
__device__ __half g_Hh[(size_t)CAP * FFN];
__device__ __half g_Yh[(size_t)CAP * HID];

// ---------------- helpers ----------------
__device__ __forceinline__ uint32_t smem_u32(const void* p) {
    uint32_t a;
    asm("{ .reg .u64 t; cvta.to.shared.u64 t, %1; cvt.u32.u64 %0, t; }" : "=r"(a) : "l"(p));
    return a;
}
__device__ __forceinline__ void cpa16(uint32_t s, const void* g) {
    asm volatile("cp.async.cg.shared.global [%0], [%1], 16;\n" :: "r"(s), "l"(g));
}
__device__ __forceinline__ void ldsm4(unsigned* r, uint32_t a) {
    asm volatile("ldmatrix.sync.aligned.m8n8.x4.shared.b16 {%0,%1,%2,%3}, [%4];"
                 : "=r"(r[0]), "=r"(r[1]), "=r"(r[2]), "=r"(r[3]) : "r"(a));
}
__device__ __forceinline__ void ldsm4t(unsigned* r, uint32_t a) {
    asm volatile("ldmatrix.sync.aligned.m8n8.x4.trans.shared.b16 {%0,%1,%2,%3}, [%4];"
                 : "=r"(r[0]), "=r"(r[1]), "=r"(r[2]), "=r"(r[3]) : "r"(a));
}
__device__ __forceinline__ void sts64(uint32_t a, uint32_t u0, uint32_t u1) {
    asm volatile("st.shared.v2.b32 [%0], {%1,%2};" :: "r"(a), "r"(u0), "r"(u1) : "memory");
}
__device__ __forceinline__ uint32_t h2u(__half2 h) {
    return *reinterpret_cast<uint32_t*>(&h);
}

// ---------------- routing ----------------
__global__ void k_router(const float* __restrict__ x, const float* __restrict__ Wr) {
    int warp = threadIdx.x >> 5, lane = threadIdx.x & 31;
    int t = blockIdx.x * 8 + warp;
    const float* xr = x + (size_t)t * HID;
    float acc[NE];
#pragma unroll
    for (int e = 0; e < NE; e++) acc[e] = 0.f;
    for (int i = lane; i < HID; i += 32) {
        float xv = xr[i];
        const float4* w = (const float4*)(Wr + (size_t)i * NE);
        float4 w0 = w[0], w1 = w[1];
        acc[0] += xv * w0.x; acc[1] += xv * w0.y; acc[2] += xv * w0.z; acc[3] += xv * w0.w;
        acc[4] += xv * w1.x; acc[5] += xv * w1.y; acc[6] += xv * w1.z; acc[7] += xv * w1.w;
    }
#pragma unroll
    for (int e = 0; e < NE; e++)
#pragma unroll
        for (int s = 16; s > 0; s >>= 1) acc[e] += __shfl_xor_sync(0xffffffffu, acc[e], s);
    if (lane == 0) {
        int i0 = 0; float m0 = acc[0];
#pragma unroll
        for (int e = 1; e < NE; e++) if (acc[e] > m0) { m0 = acc[e]; i0 = e; }
        int i1 = -1; float m1 = -1e30f;
#pragma unroll
        for (int e = 0; e < NE; e++) if (e != i0 && acc[e] > m1) { m1 = acc[e]; i1 = e; }
        float w0 = 1.f / (1.f + expf(m1 - m0));
        g_tok2[2 * t] = i0; g_tok2[2 * t + 1] = i1;
        g_w2v[2 * t] = w0;  g_w2v[2 * t + 1] = 1.f - w0;
        atomicAdd(&g_cnt[i0], 1);
        atomicAdd(&g_cnt[i1], 1);
    }
}

// reads counters, builds offsets, then re-zeroes counters for the next replay.
// (device globals are zero-initialized at load, so the first execution is
// consistent too; every execution performs identical work.)
__global__ void k_offsets() {
    if (threadIdx.x == 0) {
        int o = 0;
#pragma unroll
        for (int e = 0; e < NE; e++) {
            int c = g_cnt[e];
            g_off[e] = o; g_end[e] = o + c; g_cur[e] = o;
            o += (c + 127) & ~127;
            g_cnt[e] = 0;
        }
        g_off[NE] = o;
    }
}

__global__ void k_place() {
    int p = blockIdx.x * blockDim.x + threadIdx.x;
    if (p < NTOK * 2) {
        int e = g_tok2[p];
        int r = atomicAdd(&g_cur[e], 1);
        g_rowTok[r] = p >> 1;
        g_pairPos[p] = r;
    }
}

// gather + fp16-convert x into g_Xh; zero pad rows
__global__ void k_gather(const float* __restrict__ x) {
    int r = blockIdx.x;
    bool valid = false;
#pragma unroll
    for (int e = 0; e < NE; e++) valid |= (r >= g_off[e] && r < g_end[e]);
    __half2* dst = (__half2*)(g_Xh + (size_t)r * HID);
    int i = threadIdx.x;  // 256 threads * 4 floats
    if (valid) {
        const float4* src = (const float4*)(x + (size_t)g_rowTok[r] * HID);
        float4 v = src[i];
        dst[2 * i]     = __floats2half2_rn(v.x, v.y);
        dst[2 * i + 1] = __floats2half2_rn(v.z, v.w);
    } else {
        dst[2 * i]     = __floats2half2_rn(0.f, 0.f);
        dst[2 * i + 1] = __floats2half2_rn(0.f, 0.f);
    }
}

// ---------------- pipelined FP16 mma.sync grouped GEMM, fused B fp32->fp16 ----------------
// CTA 128x128, 4 warps (2x2) of 64x64. A: 4-stage cp.async (fp16 source).
// B: fp32 weights streamed via LDG.128 one iteration ahead, converted to fp16
//    at STS time into a 2-buffer smem ring. 2 CTAs/SM.
template <int KD, int ND, bool DOGELU>
__global__ void __launch_bounds__(128, 2)
k_hgemm(const float* __restrict__ Bsrc, const float* __restrict__ Bias) {
    extern __shared__ char smem[];

    int row0 = blockIdx.y * BM;
    if (row0 >= g_off[NE]) return;
    int e = 0;
    while (row0 >= g_off[e + 1]) e++;
    int nblk = blockIdx.x * BN;

    const __half* A  = DOGELU ? g_Xh : g_Hh;
    const float* B32 = Bsrc + (size_t)e * KD * ND;

    int tid = threadIdx.x;
    uint32_t sb = smem_u32(smem);

    // A cp.async slots: 128 rows x 4 chunks of 16B (8 halves)
    const __half* aS[4]; uint32_t aD[4];
#pragma unroll
    for (int p = 0; p < 4; p++) {
        int i = tid + 128 * p;
        int r = i >> 2, j = i & 3;
        aS[p] = A + (size_t)(row0 + r) * KD + j * 8;
        aD[p] = sb + r * (APAD * 2) + j * 16;
    }

    // B LDG slots: 32 k-rows x 32 chunks of 4 floats (16B)
    const float4* bG[8]; uint32_t bD[8];
#pragma unroll
    for (int p = 0; p < 8; p++) {
        int c = tid + 128 * p;
        int kr = c >> 5, j = c & 31;
        bG[p] = (const float4*)(B32 + (size_t)kr * ND + nblk + j * 4);
        bD[p] = sb + A_TOT + kr * (BPAD * 2) + j * 8;
    }

    const int NKT = KD / BK;
    const size_t BSTEP4 = (size_t)BK * ND / 4;   // float4 step per kt

    auto LOADA = [&](int kt) {
        uint32_t st = (kt % STAGES) * ABYTES;
        size_t ka = (size_t)kt * BK;
#pragma unroll
        for (int p = 0; p < 4; p++) cpa16(aD[p] + st, aS[p] + ka);
        asm volatile("cp.async.commit_group;" ::: "memory");
    };

    float4 b4[8];
    auto LDGB = [&](int kt) {
        size_t o = (size_t)kt * BSTEP4;
#pragma unroll
        for (int p = 0; p < 8; p++) b4[p] = __ldg(bG[p] + o);
    };
    auto STSB = [&](int kt) {
        uint32_t st = (kt & 1) * BBYTES;
#pragma unroll
        for (int p = 0; p < 8; p++) {
            uint32_t u0 = h2u(__floats2half2_rn(b4[p].x, b4[p].y));
            uint32_t u1 = h2u(__floats2half2_rn(b4[p].z, b4[p].w));
            sts64(bD[p] + st, u0, u1);
        }
    };

    LOADA(0); LOADA(1); LOADA(2);
    LDGB(0);

    float acc[4][8][4];
#pragma unroll
    for (int mi = 0; mi < 4; mi++)
#pragma unroll
        for (int ni = 0; ni < 8; ni++)
#pragma unroll
            for (int q = 0; q < 4; q++) acc[mi][ni][q] = 0.f;

    int wid = tid >> 5, lane = tid & 31;
    int g = lane >> 2, tg = lane & 3;
    int wm = (wid >> 1) * 64, wn = (wid & 1) * 64;
    int lane8 = lane & 7, laneb = (lane >> 3) & 1, laneh = lane >> 4;

    uint32_t aAddr0 = sb + ((wm + lane8 + laneb * 8) * APAD + laneh * 8) * 2;
    uint32_t bAddr0 = sb + A_TOT + ((lane8 + laneb * 8) * BPAD + wn + laneh * 8) * 2;

    for (int kt = 0; kt < NKT; kt++) {
        asm volatile("cp.async.wait_group %0;" :: "n"(STAGES - 2));
        STSB(kt);
        __syncthreads();
        if (kt + STAGES - 1 < NKT) LOADA(kt + STAGES - 1);
        else asm volatile("cp.async.commit_group;" ::: "memory");
        if (kt + 1 < NKT) LDGB(kt + 1);

        uint32_t stA = (kt % STAGES) * ABYTES;
        uint32_t stB = (kt & 1) * BBYTES;
#pragma unroll
        for (int ks = 0; ks < BK; ks += 16) {
            unsigned af[4][4], bf[8][2];
#pragma unroll
            for (int mi = 0; mi < 4; mi++)
                ldsm4(af[mi], aAddr0 + stA + (mi * 16 * APAD + ks) * 2);
#pragma unroll
            for (int np = 0; np < 4; np++) {
                unsigned r[4];
                ldsm4t(r, bAddr0 + stB + (ks * BPAD + np * 16) * 2);
                bf[2 * np][0] = r[0]; bf[2 * np][1] = r[1];
                bf[2 * np + 1][0] = r[2]; bf[2 * np + 1][1] = r[3];
            }
#pragma unroll
            for (int mi = 0; mi < 4; mi++)
#pragma unroll
                for (int ni = 0; ni < 8; ni++) {
                    asm volatile(
                        "mma.sync.aligned.m16n8k16.row.col.f32.f16.f16.f32 "
                        "{%0,%1,%2,%3}, {%4,%5,%6,%7}, {%8,%9}, {%0,%1,%2,%3};\n"
                        : "+f"(acc[mi][ni][0]), "+f"(acc[mi][ni][1]),
                          "+f"(acc[mi][ni][2]), "+f"(acc[mi][ni][3])
                        : "r"(af[mi][0]), "r"(af[mi][1]), "r"(af[mi][2]), "r"(af[mi][3]),
                          "r"(bf[ni][0]), "r"(bf[ni][1]));
                }
        }
    }

    asm volatile("cp.async.wait_group 0;" ::: "memory");

    // epilogue
    const float* bias = Bias + (size_t)e * ND + nblk;
    float bv[16];
#pragma unroll
    for (int ni = 0; ni < 8; ni++) {
        bv[2 * ni]     = bias[wn + ni * 8 + 2 * tg];
        bv[2 * ni + 1] = bias[wn + ni * 8 + 2 * tg + 1];
    }
#pragma unroll
    for (int mi = 0; mi < 4; mi++) {
        int rr = row0 + wm + mi * 16 + g;
#pragma unroll
        for (int ni = 0; ni < 8; ni++) {
            float v0 = acc[mi][ni][0] + bv[2 * ni];
            float v1 = acc[mi][ni][1] + bv[2 * ni + 1];
            float v2 = acc[mi][ni][2] + bv[2 * ni];
            float v3 = acc[mi][ni][3] + bv[2 * ni + 1];
            int nc = wn + ni * 8 + 2 * tg;
            if (DOGELU) {
                v0 = 0.5f * v0 * (1.f + erff(v0 * 0.70710678118654752f));
                v1 = 0.5f * v1 * (1.f + erff(v1 * 0.70710678118654752f));
                v2 = 0.5f * v2 * (1.f + erff(v2 * 0.70710678118654752f));
                v3 = 0.5f * v3 * (1.f + erff(v3 * 0.70710678118654752f));
                __half2* h0 = (__half2*)(g_Hh + (size_t)rr * ND + nblk + nc);
                __half2* h1 = (__half2*)(g_Hh + (size_t)(rr + 8) * ND + nblk + nc);
                *h0 = __floats2half2_rn(v0, v1);
                *h1 = __floats2half2_rn(v2, v3);
            } else {
                __half2* y0 = (__half2*)(g_Yh + (size_t)rr * ND + nblk + nc);
                __half2* y1 = (__half2*)(g_Yh + (size_t)(rr + 8) * ND + nblk + nc);
                *y0 = __floats2half2_rn(v0, v1);
                *y1 = __floats2half2_rn(v2, v3);
            }
        }
    }
}

// ---------------- combine: out[t] = w0*Y[pos0] + w1*Y[pos1]  (fp16 Y, fp32 out) ----------------
__global__ void k_combine(float* __restrict__ out) {
    int t = blockIdx.x;
    int p0 = g_pairPos[2 * t], p1 = g_pairPos[2 * t + 1];
    float w0 = g_w2v[2 * t], w1 = g_w2v[2 * t + 1];
    const uint4* y0 = (const uint4*)(g_Yh + (size_t)p0 * HID);
    const uint4* y1 = (const uint4*)(g_Yh + (size_t)p1 * HID);
    float4* o = (float4*)(out + (size_t)t * HID);
    int i = threadIdx.x;                 // 128 threads * 8 halves
    uint4 a = y0[i], b = y1[i];
    const __half2* ah = (const __half2*)&a;
    const __half2* bh = (const __half2*)&b;
    float4 r0, r1;
    float2 a0 = __half22float2(ah[0]), b0 = __half22float2(bh[0]);
    float2 a1 = __half22float2(ah[1]), b1 = __half22float2(bh[1]);
    float2 a2 = __half22float2(ah[2]), b2 = __half22float2(bh[2]);
    float2 a3 = __half22float2(ah[3]), b3 = __half22float2(bh[3]);
    r0.x = w0 * a0.x + w1 * b0.x;  r0.y = w0 * a0.y + w1 * b0.y;
    r0.z = w0 * a1.x + w1 * b1.x;  r0.w = w0 * a1.y + w1 * b1.y;
    r1.x = w0 * a2.x + w1 * b2.x;  r1.y = w0 * a2.y + w1 * b2.y;
    r1.z = w0 * a3.x + w1 * b3.x;  r1.w = w0 * a3.y + w1 * b3.y;
    o[2 * i]     = r0;
    o[2 * i + 1] = r1;
}

// ---------------- launch ----------------
extern "C" void kernel_launch(void* const* d_in, const int* in_sizes, int n_in,
                              void* d_out, int out_size) {
    const float* x  = (const float*)d_in[0];
    const float* Wr = (const float*)d_in[1];
    const float* W1 = (const float*)d_in[2];
    const float* b1 = (const float*)d_in[3];
    const float* W2 = (const float*)d_in[4];
    const float* b2 = (const float*)d_in[5];
    float* out = (float*)d_out;

    cudaFuncSetAttribute(k_hgemm<HID, FFN, true>,
                         cudaFuncAttributeMaxDynamicSharedMemorySize, SMEM_TOTAL);
    cudaFuncSetAttribute(k_hgemm<FFN, HID, false>,
                         cudaFuncAttributeMaxDynamicSharedMemorySize, SMEM_TOTAL);

    k_router<<<NTOK / 8, 256>>>(x, Wr);
    k_offsets<<<1, 32>>>();
    k_place<<<(NTOK * 2) / 256, 256>>>();
    k_gather<<<CAP, 256>>>(x);

    k_hgemm<HID, FFN, true><<<dim3(FFN / BN, CAP / BM), 128, SMEM_TOTAL>>>(W1, b1);
    k_hgemm<FFN, HID, false><<<dim3(HID / BN, CAP / BM), 128, SMEM_TOTAL>>>(W2, b2);
    k_combine<<<NTOK, 128>>>(out);
}

// round 9
// speedup vs baseline: 1.0624x; 1.0624x over previous
#include <cuda_runtime.h>
#include <cuda_fp16.h>
#include <math.h>
#include <stdint.h>

#define HID  1024
#define FFN  4096
#define NE   8
#define NTOK 4096
#define CAP  9216

#define BM 128
#define BN 128
#define BK 32
#define STAGES 4
#define APAD 40                        // halves per A smem row (80 B, conflict-free LDSM)
#define BPAD 136                       // halves per B smem k-row (272 B, conflict-free LDSM)
#define ABYTES (BM * APAD * 2)         // 10240
#define BBYTES (BK * BPAD * 2)         // 8704
#define STGB   (ABYTES + BBYTES)       // 18944
#define SMEM_TOTAL (STAGES * STGB)     // 75776 -> 2 CTAs/SM

#define NW4 (NE * HID * FFN / 4)       // float4 count of one weight slab

// ---------------- scratch (device globals; zero-initialized at load) ----------------
__device__ int    g_cnt[NE];
__device__ int    g_off[NE + 1];
__device__ int    g_end[NE];
__device__ int    g_cur[NE];
__device__ int    g_rowTok[CAP];
__device__ int    g_tok2[NTOK * 2];
__device__ float  g_w2v[NTOK * 2];
__device__ int    g_pairPos[NTOK * 2];
__device__ __half g_Xh[(size_t)CAP * HID];
__device__ __half g_Hh[(size_t)CAP * FFN];
__device__ __half g_Yh[(size_t)CAP * HID];
__device__ __half g_W1h[(size_t)NE * HID * FFN];
__device__ __half g_W2h[(size_t)NE * FFN * HID];

// ---------------- helpers ----------------
__device__ __forceinline__ uint32_t smem_u32(const void* p) {
    uint32_t a;
    asm("{ .reg .u64 t; cvta.to.shared.u64 t, %1; cvt.u32.u64 %0, t; }" : "=r"(a) : "l"(p));
    return a;
}
__device__ __forceinline__ void cpa16(uint32_t s, const void* g) {
    asm volatile("cp.async.cg.shared.global [%0], [%1], 16;\n" :: "r"(s), "l"(g));
}
__device__ __forceinline__ void ldsm4(unsigned* r, uint32_t a) {
    asm volatile("ldmatrix.sync.aligned.m8n8.x4.shared.b16 {%0,%1,%2,%3}, [%4];"
                 : "=r"(r[0]), "=r"(r[1]), "=r"(r[2]), "=r"(r[3]) : "r"(a));
}
__device__ __forceinline__ void ldsm4t(unsigned* r, uint32_t a) {
    asm volatile("ldmatrix.sync.aligned.m8n8.x4.trans.shared.b16 {%0,%1,%2,%3}, [%4];"
                 : "=r"(r[0]), "=r"(r[1]), "=r"(r[2]), "=r"(r[3]) : "r"(a));
}

// ---------------- router (+ fused W1 fp32->fp16 conversion) ----------------
__global__ void k_router(const float* __restrict__ x, const float* __restrict__ Wr,
                         const float* __restrict__ W1) {
    int warp = threadIdx.x >> 5, lane = threadIdx.x & 31;
    int t = blockIdx.x * 8 + warp;
    const float* xr = x + (size_t)t * HID;
    float acc[NE];
#pragma unroll
    for (int e = 0; e < NE; e++) acc[e] = 0.f;
    for (int i = lane; i < HID; i += 32) {
        float xv = xr[i];
        const float4* w = (const float4*)(Wr + (size_t)i * NE);
        float4 w0 = w[0], w1 = w[1];
        acc[0] += xv * w0.x; acc[1] += xv * w0.y; acc[2] += xv * w0.z; acc[3] += xv * w0.w;
        acc[4] += xv * w1.x; acc[5] += xv * w1.y; acc[6] += xv * w1.z; acc[7] += xv * w1.w;
    }
#pragma unroll
    for (int e = 0; e < NE; e++)
#pragma unroll
        for (int s = 16; s > 0; s >>= 1) acc[e] += __shfl_xor_sync(0xffffffffu, acc[e], s);
    if (lane == 0) {
        int i0 = 0; float m0 = acc[0];
#pragma unroll
        for (int e = 1; e < NE; e++) if (acc[e] > m0) { m0 = acc[e]; i0 = e; }
        int i1 = -1; float m1 = -1e30f;
#pragma unroll
        for (int e = 0; e < NE; e++) if (e != i0 && acc[e] > m1) { m1 = acc[e]; i1 = e; }
        float w0 = 1.f / (1.f + expf(m1 - m0));
        g_tok2[2 * t] = i0; g_tok2[2 * t + 1] = i1;
        g_w2v[2 * t] = w0;  g_w2v[2 * t + 1] = 1.f - w0;
        atomicAdd(&g_cnt[i0], 1);
        atomicAdd(&g_cnt[i1], 1);
    }
    // fused W1 conversion (all threads; independent of routing math above)
    {
        const float4* s = (const float4*)W1;
        __half2* d = (__half2*)g_W1h;
        int stride = gridDim.x * blockDim.x;
        for (int i = blockIdx.x * blockDim.x + threadIdx.x; i < NW4; i += stride) {
            float4 v = s[i];
            d[2 * i]     = __floats2half2_rn(v.x, v.y);
            d[2 * i + 1] = __floats2half2_rn(v.z, v.w);
        }
    }
}

// reads counters, builds offsets, then re-zeroes counters for the next replay.
__global__ void k_offsets() {
    if (threadIdx.x == 0) {
        int o = 0;
#pragma unroll
        for (int e = 0; e < NE; e++) {
            int c = g_cnt[e];
            g_off[e] = o; g_end[e] = o + c; g_cur[e] = o;
            o += (c + 127) & ~127;
            g_cnt[e] = 0;
        }
        g_off[NE] = o;
    }
}

__global__ void k_place() {
    int p = blockIdx.x * blockDim.x + threadIdx.x;
    if (p < NTOK * 2) {
        int e = g_tok2[p];
        int r = atomicAdd(&g_cur[e], 1);
        g_rowTok[r] = p >> 1;
        g_pairPos[p] = r;
    }
}

// gather + fp16-convert x into g_Xh; zero pad rows
__global__ void k_gather(const float* __restrict__ x) {
    int r = blockIdx.x;
    bool valid = false;
#pragma unroll
    for (int e = 0; e < NE; e++) valid |= (r >= g_off[e] && r < g_end[e]);
    __half2* dst = (__half2*)(g_Xh + (size_t)r * HID);
    int i = threadIdx.x;  // 256 threads * 4 floats
    if (valid) {
        const float4* src = (const float4*)(x + (size_t)g_rowTok[r] * HID);
        float4 v = src[i];
        dst[2 * i]     = __floats2half2_rn(v.x, v.y);
        dst[2 * i + 1] = __floats2half2_rn(v.z, v.w);
    } else {
        dst[2 * i]     = __floats2half2_rn(0.f, 0.f);
        dst[2 * i + 1] = __floats2half2_rn(0.f, 0.f);
    }
}

// ---------------- pipelined FP16 mma.sync grouped GEMM ----------------
// CTA 128x128, 4 warps (2x2) of 64x64, BK=32, 4-stage cp.async, 2 CTAs/SM.
// CONVW2: GEMM1 CTAs convert their share of W2 fp32->fp16 as a prologue
// (registers dead before the mainloop; DRAM work hides under other CTAs' MMA).
template <int KD, int ND, bool DOGELU, bool CONVW2>
__global__ void __launch_bounds__(128, 2)
k_hgemm(const float* __restrict__ Bias, const float* __restrict__ ConvSrc) {
    extern __shared__ char smem[];
    int tid = threadIdx.x;

    if (CONVW2) {
        const float4* s = (const float4*)ConvSrc;
        __half2* d = (__half2*)g_W2h;
        int cta = blockIdx.y * gridDim.x + blockIdx.x;
        int stride = gridDim.x * gridDim.y * 128;
        for (int i = cta * 128 + tid; i < NW4; i += stride) {
            float4 v = s[i];
            d[2 * i]     = __floats2half2_rn(v.x, v.y);
            d[2 * i + 1] = __floats2half2_rn(v.z, v.w);
        }
    }

    int row0 = blockIdx.y * BM;
    if (row0 >= g_off[NE]) return;
    int e = 0;
    while (row0 >= g_off[e + 1]) e++;
    int nblk = blockIdx.x * BN;

    const __half* A = DOGELU ? g_Xh : g_Hh;
    const __half* B = (DOGELU ? g_W1h : g_W2h) + (size_t)e * KD * ND;

    uint32_t sb = smem_u32(smem);

    // cp.async slots: A = 128 rows x 4 chunks(16B=8 halves); B = 32 k-rows x 16 chunks
    const __half* aS[4]; uint32_t aD[4];
    const __half* bS[4]; uint32_t bD[4];
#pragma unroll
    for (int p = 0; p < 4; p++) {
        int i = tid + 128 * p;
        int r = i >> 2, j = i & 3;
        aS[p] = A + (size_t)(row0 + r) * KD + j * 8;
        aD[p] = sb + r * (APAD * 2) + j * 16;
    }
#pragma unroll
    for (int p = 0; p < 4; p++) {
        int i = tid + 128 * p;
        int kr = i >> 4, j = i & 15;
        bS[p] = B + (size_t)kr * ND + nblk + j * 8;
        bD[p] = sb + ABYTES + kr * (BPAD * 2) + j * 16;
    }

    const int NKT = KD / BK;

    auto LOAD = [&](int kt) {
        uint32_t st = (kt % STAGES) * STGB;
        size_t ka = (size_t)kt * BK;
        size_t kb = (size_t)kt * BK * ND;
#pragma unroll
        for (int p = 0; p < 4; p++) cpa16(aD[p] + st, aS[p] + ka);
#pragma unroll
        for (int p = 0; p < 4; p++) cpa16(bD[p] + st, bS[p] + kb);
        asm volatile("cp.async.commit_group;" ::: "memory");
    };

    LOAD(0); LOAD(1); LOAD(2);

    float acc[4][8][4];
#pragma unroll
    for (int mi = 0; mi < 4; mi++)
#pragma unroll
        for (int ni = 0; ni < 8; ni++)
#pragma unroll
            for (int q = 0; q < 4; q++) acc[mi][ni][q] = 0.f;

    int wid = tid >> 5, lane = tid & 31;
    int g = lane >> 2, tg = lane & 3;
    int wm = (wid >> 1) * 64, wn = (wid & 1) * 64;
    int lane8 = lane & 7, laneb = (lane >> 3) & 1, laneh = lane >> 4;

    uint32_t aAddr0 = sb + ((wm + lane8 + laneb * 8) * APAD + laneh * 8) * 2;
    uint32_t bAddr0 = sb + ABYTES + ((lane8 + laneb * 8) * BPAD + wn + laneh * 8) * 2;

    for (int kt = 0; kt < NKT; kt++) {
        asm volatile("cp.async.wait_group %0;" :: "n"(STAGES - 2));
        __syncthreads();
        if (kt + STAGES - 1 < NKT) LOAD(kt + STAGES - 1);
        else asm volatile("cp.async.commit_group;" ::: "memory");

        uint32_t st = (kt % STAGES) * STGB;
#pragma unroll
        for (int ks = 0; ks < BK; ks += 16) {
            unsigned af[4][4], bf[8][2];
#pragma unroll
            for (int mi = 0; mi < 4; mi++)
                ldsm4(af[mi], aAddr0 + st + (mi * 16 * APAD + ks) * 2);
#pragma unroll
            for (int np = 0; np < 4; np++) {
                unsigned r[4];
                ldsm4t(r, bAddr0 + st + (ks * BPAD + np * 16) * 2);
                bf[2 * np][0] = r[0]; bf[2 * np][1] = r[1];
                bf[2 * np + 1][0] = r[2]; bf[2 * np + 1][1] = r[3];
            }
#pragma unroll
            for (int mi = 0; mi < 4; mi++)
#pragma unroll
                for (int ni = 0; ni < 8; ni++) {
                    asm volatile(
                        "mma.sync.aligned.m16n8k16.row.col.f32.f16.f16.f32 "
                        "{%0,%1,%2,%3}, {%4,%5,%6,%7}, {%8,%9}, {%0,%1,%2,%3};\n"
                        : "+f"(acc[mi][ni][0]), "+f"(acc[mi][ni][1]),
                          "+f"(acc[mi][ni][2]), "+f"(acc[mi][ni][3])
                        : "r"(af[mi][0]), "r"(af[mi][1]), "r"(af[mi][2]), "r"(af[mi][3]),
                          "r"(bf[ni][0]), "r"(bf[ni][1]));
                }
        }
    }

    asm volatile("cp.async.wait_group 0;" ::: "memory");

    // epilogue
    const float* bias = Bias + (size_t)e * ND + nblk;
    float bv[16];
#pragma unroll
    for (int ni = 0; ni < 8; ni++) {
        bv[2 * ni]     = bias[wn + ni * 8 + 2 * tg];
        bv[2 * ni + 1] = bias[wn + ni * 8 + 2 * tg + 1];
    }
#pragma unroll
    for (int mi = 0; mi < 4; mi++) {
        int rr = row0 + wm + mi * 16 + g;
#pragma unroll
        for (int ni = 0; ni < 8; ni++) {
            float v0 = acc[mi][ni][0] + bv[2 * ni];
            float v1 = acc[mi][ni][1] + bv[2 * ni + 1];
            float v2 = acc[mi][ni][2] + bv[2 * ni];
            float v3 = acc[mi][ni][3] + bv[2 * ni + 1];
            int nc = wn + ni * 8 + 2 * tg;
            if (DOGELU) {
                v0 = 0.5f * v0 * (1.f + erff(v0 * 0.70710678118654752f));
                v1 = 0.5f * v1 * (1.f + erff(v1 * 0.70710678118654752f));
                v2 = 0.5f * v2 * (1.f + erff(v2 * 0.70710678118654752f));
                v3 = 0.5f * v3 * (1.f + erff(v3 * 0.70710678118654752f));
                __half2* h0 = (__half2*)(g_Hh + (size_t)rr * ND + nblk + nc);
                __half2* h1 = (__half2*)(g_Hh + (size_t)(rr + 8) * ND + nblk + nc);
                *h0 = __floats2half2_rn(v0, v1);
                *h1 = __floats2half2_rn(v2, v3);
            } else {
                __half2* y0 = (__half2*)(g_Yh + (size_t)rr * ND + nblk + nc);
                __half2* y1 = (__half2*)(g_Yh + (size_t)(rr + 8) * ND + nblk + nc);
                *y0 = __floats2half2_rn(v0, v1);
                *y1 = __floats2half2_rn(v2, v3);
            }
        }
    }
}

// ---------------- combine: out[t] = w0*Y[pos0] + w1*Y[pos1]  (fp16 Y, fp32 out) ----------------
__global__ void k_combine(float* __restrict__ out) {
    int t = blockIdx.x;
    int p0 = g_pairPos[2 * t], p1 = g_pairPos[2 * t + 1];
    float w0 = g_w2v[2 * t], w1 = g_w2v[2 * t + 1];
    const uint4* y0 = (const uint4*)(g_Yh + (size_t)p0 * HID);
    const uint4* y1 = (const uint4*)(g_Yh + (size_t)p1 * HID);
    float4* o = (float4*)(out + (size_t)t * HID);
    int i = threadIdx.x;                 // 128 threads * 8 halves
    uint4 a = y0[i], b = y1[i];
    const __half2* ah = (const __half2*)&a;
    const __half2* bh = (const __half2*)&b;
    float4 r0, r1;
    float2 a0 = __half22float2(ah[0]), b0 = __half22float2(bh[0]);
    float2 a1 = __half22float2(ah[1]), b1 = __half22float2(bh[1]);
    float2 a2 = __half22float2(ah[2]), b2 = __half22float2(bh[2]);
    float2 a3 = __half22float2(ah[3]), b3 = __half22float2(bh[3]);
    r0.x = w0 * a0.x + w1 * b0.x;  r0.y = w0 * a0.y + w1 * b0.y;
    r0.z = w0 * a1.x + w1 * b1.x;  r0.w = w0 * a1.y + w1 * b1.y;
    r1.x = w0 * a2.x + w1 * b2.x;  r1.y = w0 * a2.y + w1 * b2.y;
    r1.z = w0 * a3.x + w1 * b3.x;  r1.w = w0 * a3.y + w1 * b3.y;
    o[2 * i]     = r0;
    o[2 * i + 1] = r1;
}

// ---------------- launch ----------------
extern "C" void kernel_launch(void* const* d_in, const int* in_sizes, int n_in,
                              void* d_out, int out_size) {
    const float* x  = (const float*)d_in[0];
    const float* Wr = (const float*)d_in[1];
    const float* W1 = (const float*)d_in[2];
    const float* b1 = (const float*)d_in[3];
    const float* W2 = (const float*)d_in[4];
    const float* b2 = (const float*)d_in[5];
    float* out = (float*)d_out;

    cudaFuncSetAttribute((const void*)k_hgemm<HID, FFN, true, true>,
                         cudaFuncAttributeMaxDynamicSharedMemorySize, SMEM_TOTAL);
    cudaFuncSetAttribute((const void*)k_hgemm<FFN, HID, false, false>,
                         cudaFuncAttributeMaxDynamicSharedMemorySize, SMEM_TOTAL);

    k_router<<<NTOK / 8, 256>>>(x, Wr, W1);
    k_offsets<<<1, 32>>>();
    k_place<<<(NTOK * 2) / 256, 256>>>();
    k_gather<<<CAP, 256>>>(x);

    k_hgemm<HID, FFN, true, true><<<dim3(FFN / BN, CAP / BM), 128, SMEM_TOTAL>>>(b1, W2);
    k_hgemm<FFN, HID, false, false><<<dim3(HID / BN, CAP / BM), 128, SMEM_TOTAL>>>(b2, nullptr);
    k_combine<<<NTOK, 128>>>(out);
}